// round 4
// baseline (speedup 1.0000x reference)
#include <cuda_runtime.h>
#include <cstdint>

// Problem constants (fixed by reference setup_inputs)
#define B_   4
#define N_   16384
#define C_   64
#define NQ_  256
#define NS_  32

// Output layout (verified passing in R1):
//   grouped_xyz : [B, 3,   NQ, NS]
//   new_features: [B, 3+C, NQ, NS]
//   mask        : [B, NQ, NS]  (all False; index 0 can only land in slot 0,
//                               which the reference forces to False)

__global__ __launch_bounds__(256) void boxquery_group_kernel(
    const float* __restrict__ xyz,    // [B, N, 3]
    const float* __restrict__ feat,   // [B, C, N]
    const float* __restrict__ qbox,   // [B, NQ, 6]
    float* __restrict__ out)
{
    const int bq   = blockIdx.x;        // 0 .. B*NQ-1
    const int b    = bq >> 8;           // / NQ_
    const int q    = bq & (NQ_ - 1);
    const int tid  = threadIdx.x;
    const int lane = tid & 31;
    const int w    = tid >> 5;

    __shared__ float    spx[256], spy[256], spz[256];
    __shared__ unsigned smask[8];
    __shared__ int      sidx_fb[NS_];   // fallback only

    // Box parameters (broadcast loads)
    const float* box = qbox + (size_t)(b * NQ_ + q) * 6;
    const float cx = box[0], cy = box[1], cz = box[2];
    const float hx = 0.5f * box[3], hy = 0.5f * box[4], hz = 0.5f * box[5];

    const float* xb = xyz + (size_t)b * N_ * 3;

    // ---- Phase 1: all 256 threads test point n = tid in parallel ----
    // selection predicate ("sort key == 0"): (n == 0) || !in_box(n)
    {
        const float px = xb[tid * 3 + 0];
        const float py = xb[tid * 3 + 1];
        const float pz = xb[tid * 3 + 2];
        spx[tid] = px; spy[tid] = py; spz[tid] = pz;
        const bool inb = (fabsf(px - cx) <= hx) &
                         (fabsf(py - cy) <= hy) &
                         (fabsf(pz - cz) <= hz);
        const bool acc = (tid == 0) || (!inb);
        const unsigned m = __ballot_sync(0xffffffffu, acc);
        if (lane == 0) smask[w] = m;
    }
    __syncthreads();

    // ---- Phase 2: every thread resolves the index for its own k = lane ----
    unsigned m0 = smask[0], m1 = smask[1], m2 = smask[2], m3 = smask[3];
    unsigned m4 = smask[4], m5 = smask[5], m6 = smask[6], m7 = smask[7];
    const int total = __popc(m0) + __popc(m1) + __popc(m2) + __popc(m3) +
                      __popc(m4) + __popc(m5) + __popc(m6) + __popc(m7);

    int n;  // selected point index for slot k = lane
    if (total >= NS_) {
        // k-th set bit across concatenated masks (pure ALU, ~16 ops)
        unsigned mm[8] = {m0, m1, m2, m3, m4, m5, m6, m7};
        int rem = lane;
        n = -1;
        #pragma unroll
        for (int ww = 0; ww < 8; ++ww) {
            const int c = __popc(mm[ww]);
            if (n < 0) {
                if (rem < c) n = ww * 32 + (int)__fns(mm[ww], 0, rem + 1);
                else         rem -= c;
            }
        }
    } else {
        // ---- Fallback (statistically never taken): exact argsort semantics.
        // First all zero-key entries ascending, then in-box (n>0) ascending.
        if (w == 0) {
            int count = 0, base = 0;
            while (count < NS_ && base < N_) {
                const int nn = base + lane;
                const float px = xb[nn * 3 + 0];
                const float py = xb[nn * 3 + 1];
                const float pz = xb[nn * 3 + 2];
                const bool inb = (fabsf(px - cx) <= hx) &
                                 (fabsf(py - cy) <= hy) &
                                 (fabsf(pz - cz) <= hz);
                const bool acc = (nn == 0) || (!inb);
                const unsigned m   = __ballot_sync(0xffffffffu, acc);
                const int      pre = __popc(m & ((1u << lane) - 1u));
                if (acc && count + pre < NS_) sidx_fb[count + pre] = nn;
                count += __popc(m);
                base  += 32;
            }
            base = 0;
            while (count < NS_ && base < N_) {
                const int nn = base + lane;
                const float px = xb[nn * 3 + 0];
                const float py = xb[nn * 3 + 1];
                const float pz = xb[nn * 3 + 2];
                const bool inb = (fabsf(px - cx) <= hx) &
                                 (fabsf(py - cy) <= hy) &
                                 (fabsf(pz - cz) <= hz);
                const bool acc = (nn != 0) && inb;
                const unsigned m   = __ballot_sync(0xffffffffu, acc);
                const int      pre = __popc(m & ((1u << lane) - 1u));
                if (acc && count + pre < NS_) sidx_fb[count + pre] = nn;
                count += __popc(m);
                base  += 32;
            }
        }
        __syncthreads();
        n = sidx_fb[lane];
    }

    // ---- Phase 3: outputs ----
    float* out_gx = out;                                        // [B,3,NQ,NS]
    float* out_nf = out + (size_t)B_ * 3 * NQ_ * NS_;           // [B,3+C,NQ,NS]
    float* out_mk = out_nf + (size_t)B_ * (3 + C_) * NQ_ * NS_; // [B,NQ,NS]

    // grouped xyz values for slot k=lane (shared in main path, global in fallback)
    float gx, gy, gz;
    if (n < 256) { gx = spx[n] - cx; gy = spy[n] - cy; gz = spz[n] - cz; }
    else {
        gx = xb[n * 3 + 0] - cx;
        gy = xb[n * 3 + 1] - cy;
        gz = xb[n * 3 + 2] - cz;
    }

    if (tid < 3 * NS_) {
        const int d = w;                 // 0,1,2 for warps 0..2
        const float v = (d == 0) ? gx : (d == 1) ? gy : gz;
        out_gx[((size_t)(b * 3 + d) * NQ_ + q) * NS_ + lane]        = v;
        out_nf[((size_t)(b * (3 + C_) + d) * NQ_ + q) * NS_ + lane] = v;
    } else if (tid < 4 * NS_) {
        out_mk[(size_t)(b * NQ_ + q) * NS_ + lane] = 0.0f;
    }

    // feature channels: thread handles (c = w + 8j, k = lane), j = 0..7
    const float* fb = feat + (size_t)b * C_ * N_;
    float vals[8];
    #pragma unroll
    for (int j = 0; j < 8; ++j) {
        const int c = w + 8 * j;
        vals[j] = fb[(size_t)c * N_ + n];          // 8 independent loads (MLP)
    }
    #pragma unroll
    for (int j = 0; j < 8; ++j) {
        const int c = w + 8 * j;
        out_nf[((size_t)(b * (3 + C_) + (3 + c)) * NQ_ + q) * NS_ + lane] = vals[j];
    }
}

extern "C" void kernel_launch(void* const* d_in, const int* in_sizes, int n_in,
                              void* d_out, int out_size)
{
    const float* key_xyz      = (const float*)d_in[0];  // [4,16384,3]
    const float* key_features = (const float*)d_in[1];  // [4,64,16384]
    const float* query_box    = (const float*)d_in[2];  // [4,256,6]
    float* out = (float*)d_out;

    boxquery_group_kernel<<<B_ * NQ_, 256>>>(key_xyz, key_features, query_box, out);
}

// round 5
// speedup vs baseline: 1.0295x; 1.0295x over previous
#include <cuda_runtime.h>
#include <cstdint>

// Problem constants (fixed by reference setup_inputs)
#define B_   4
#define N_   16384
#define C_   64
#define NQ_  256
#define NS_  32

// Output layout (verified passing since R1):
//   grouped_xyz : [B, 3,   NQ, NS]
//   new_features: [B, 3+C, NQ, NS]
//   mask        : [B, NQ, NS]  (all False; index 0 can only land in slot 0,
//                               which the reference forces to False)

__global__ __launch_bounds__(256) void boxquery_group_kernel(
    const float* __restrict__ xyz,    // [B, N, 3]
    const float* __restrict__ feat,   // [B, C, N]
    const float* __restrict__ qbox,   // [B, NQ, 6]
    float* __restrict__ out)
{
    const int bq   = blockIdx.x;        // 0 .. B*NQ-1
    const int b    = bq >> 8;           // / NQ_
    const int q    = bq & (NQ_ - 1);
    const int tid  = threadIdx.x;
    const int lane = tid & 31;
    const int w    = tid >> 5;

    __shared__ float spx[256], spy[256], spz[256];
    __shared__ unsigned smask[8];
    __shared__ __align__(16) int   sidx[NS_];
    __shared__ __align__(16) float sgx[3][NS_];

    // Box parameters (broadcast loads)
    const float* box = qbox + (size_t)(b * NQ_ + q) * 6;
    const float cx = box[0], cy = box[1], cz = box[2];
    const float hx = 0.5f * box[3], hy = 0.5f * box[4], hz = 0.5f * box[5];

    const float* xb = xyz + (size_t)b * N_ * 3;

    // ---- Phase 1: all 256 threads test point n = tid in parallel ----
    // selection predicate ("sort key == 0"): (n == 0) || !in_box(n)
    {
        const float px = xb[tid * 3 + 0];
        const float py = xb[tid * 3 + 1];
        const float pz = xb[tid * 3 + 2];
        spx[tid] = px; spy[tid] = py; spz[tid] = pz;
        const bool inb = (fabsf(px - cx) <= hx) &
                         (fabsf(py - cy) <= hy) &
                         (fabsf(pz - cz) <= hz);
        const bool acc = (tid == 0) || (!inb);
        const unsigned m = __ballot_sync(0xffffffffu, acc);
        if (lane == 0) smask[w] = m;
    }
    __syncthreads();

    // ---- Phase 2: warp 0 ONLY resolves the 32 selected indices ----
    if (w == 0) {
        int count = 0;
        #pragma unroll
        for (int ww = 0; ww < 8; ++ww) {
            if (count < NS_) {
                const unsigned m   = smask[ww];
                const int      pre = __popc(m & ((1u << lane) - 1u));
                if (((m >> lane) & 1u) && (count + pre) < NS_)
                    sidx[count + pre] = ww * 32 + lane;
                count += __popc(m);
            }
        }
        // ---- Fallback (statistically never taken): exact argsort order.
        // Continue zero-key scan over [256, N), then in-box (n>0) ascending.
        if (count < NS_) {
            int base = 256;
            while (count < NS_ && base < N_) {
                const int nn = base + lane;
                const float px = xb[nn * 3 + 0];
                const float py = xb[nn * 3 + 1];
                const float pz = xb[nn * 3 + 2];
                const bool inb = (fabsf(px - cx) <= hx) &
                                 (fabsf(py - cy) <= hy) &
                                 (fabsf(pz - cz) <= hz);
                const bool acc = !inb;   // nn > 0 guaranteed here
                const unsigned m   = __ballot_sync(0xffffffffu, acc);
                const int      pre = __popc(m & ((1u << lane) - 1u));
                if (acc && (count + pre) < NS_) sidx[count + pre] = nn;
                count += __popc(m);
                base  += 32;
            }
            base = 0;
            while (count < NS_ && base < N_) {
                const int nn = base + lane;
                const float px = xb[nn * 3 + 0];
                const float py = xb[nn * 3 + 1];
                const float pz = xb[nn * 3 + 2];
                const bool inb = (fabsf(px - cx) <= hx) &
                                 (fabsf(py - cy) <= hy) &
                                 (fabsf(pz - cz) <= hz);
                const bool acc = (nn != 0) && inb;
                const unsigned m   = __ballot_sync(0xffffffffu, acc);
                const int      pre = __popc(m & ((1u << lane) - 1u));
                if (acc && (count + pre) < NS_) sidx[count + pre] = nn;
                count += __popc(m);
                base  += 32;
            }
        }
        __syncwarp();
        // Centered xyz for the 32 selected points (shared-resident fast path)
        const int n = sidx[lane];
        float gx, gy, gz;
        if (n < 256) { gx = spx[n] - cx; gy = spy[n] - cy; gz = spz[n] - cz; }
        else {
            gx = xb[n * 3 + 0] - cx;
            gy = xb[n * 3 + 1] - cy;
            gz = xb[n * 3 + 2] - cz;
        }
        sgx[0][lane] = gx; sgx[1][lane] = gy; sgx[2][lane] = gz;
    }
    __syncthreads();

    // ---- Phase 3: vectorized output writes (all STG.128) ----
    float* out_gx = out;                                        // [B,3,NQ,NS]
    float* out_nf = out + (size_t)B_ * 3 * NQ_ * NS_;           // [B,3+C,NQ,NS]
    float* out_mk = out_nf + (size_t)B_ * (3 + C_) * NQ_ * NS_; // [B,NQ,NS]

    const float4* sgx4  = (const float4*)&sgx[0][0];            // [3][8]
    const int4*   sidx4 = (const int4*)sidx;                    // [8]

    if (tid < 24) {
        const int d = tid >> 3, g = tid & 7;
        const float4 v = sgx4[d * 8 + g];
        ((float4*)(out_gx + ((size_t)(b * 3 + d) * NQ_ + q) * NS_))[g]         = v;
        ((float4*)(out_nf + ((size_t)(b * (3 + C_) + d) * NQ_ + q) * NS_))[g]  = v;
    } else if (tid < 32) {
        ((float4*)(out_mk + (size_t)(b * NQ_ + q) * NS_))[tid - 24] =
            make_float4(0.f, 0.f, 0.f, 0.f);
    }

    // Feature channels: thread t -> channel c0 = t>>3 (and c0+32), k-quad g = t&7.
    const float* fb = feat + (size_t)b * C_ * N_;
    const int g  = tid & 7;
    const int c0 = tid >> 3;                 // 0..31
    const int4 nn = sidx4[g];                // one LDS.128
    float* nf_ch3 = out_nf + ((size_t)(b * (3 + C_) + 3) * NQ_ + q) * NS_;

    #pragma unroll
    for (int pass = 0; pass < 2; ++pass) {
        const int c = c0 + pass * 32;
        const float* fc = fb + (size_t)c * N_;
        float4 v;
        v.x = fc[nn.x];                      // 4 independent LDG.32 (MLP)
        v.y = fc[nn.y];
        v.z = fc[nn.z];
        v.w = fc[nn.w];
        ((float4*)(nf_ch3 + (size_t)c * NQ_ * NS_))[g] = v;   // STG.128
    }
}

extern "C" void kernel_launch(void* const* d_in, const int* in_sizes, int n_in,
                              void* d_out, int out_size)
{
    const float* key_xyz      = (const float*)d_in[0];  // [4,16384,3]
    const float* key_features = (const float*)d_in[1];  // [4,64,16384]
    const float* query_box    = (const float*)d_in[2];  // [4,256,6]
    float* out = (float*)d_out;

    boxquery_group_kernel<<<B_ * NQ_, 256>>>(key_xyz, key_features, query_box, out);
}